// round 15
// baseline (speedup 1.0000x reference)
#include <cuda_runtime.h>
#include <math.h>

#define T_SEQ 512
#define NB    64
#define NI    256
#define NH    512

// Input-projection scratch (rewritten fully every launch; no other globals).
__device__ float g_pre[(size_t)T_SEQ * NB * NH];

typedef unsigned long long ull;

// Packed 2x fp32 FMA (sm_10x f32x2 pipe).
#define FFMA2(d, a, b, c) \
    asm("fma.rn.f32x2 %0, %1, %2, %3;" : "=l"(d) : "l"(a), "l"(b), "l"(c))

__device__ __forceinline__ ull pack2(float lo, float hi) {
    ull r;
    asm("mov.b64 %0, {%1, %2};"
        : "=l"(r) : "r"(__float_as_uint(lo)), "r"(__float_as_uint(hi)));
    return r;
}
__device__ __forceinline__ float2 unpack2(ull v) {
    unsigned lo, hi;
    asm("mov.b64 {%0, %1}, %2;" : "=r"(lo), "=r"(hi) : "l"(v));
    return make_float2(__uint_as_float(lo), __uint_as_float(hi));
}
__device__ __forceinline__ unsigned smem_u32(const void* p) {
    return (unsigned)__cvta_generic_to_shared(p);
}
__device__ __forceinline__ void mbar_init(unsigned a, unsigned cnt) {
    asm volatile("mbarrier.init.shared.b64 [%0], %1;" :: "r"(a), "r"(cnt)
                 : "memory");
}
// Remote arrive with cluster-scope RELEASE (orders this lane's prior DSMEM stores).
__device__ __forceinline__ void mbar_arrive_rel_rank(unsigned laddr,
                                                     unsigned rank) {
    asm volatile(
        "{\n\t.reg .b32 ra;\n\t"
        "mapa.shared::cluster.u32 ra, %0, %1;\n\t"
        "mbarrier.arrive.release.cluster.shared::cluster.b64 _, [ra];\n\t}"
        :: "r"(laddr), "r"(rank) : "memory");
}
// Remote arrive, default semantics (read-side signal).
__device__ __forceinline__ void mbar_arrive_rank(unsigned laddr,
                                                 unsigned rank) {
    asm volatile(
        "{\n\t.reg .b32 ra;\n\t"
        "mapa.shared::cluster.u32 ra, %0, %1;\n\t"
        "mbarrier.arrive.shared::cluster.b64 _, [ra];\n\t}"
        :: "r"(laddr), "r"(rank) : "memory");
}
// Local wait, cluster-scope acquire (orders subsequent smem reads).
__device__ __forceinline__ void mbar_wait(unsigned a, unsigned parity) {
    unsigned done;
    do {
        asm volatile(
            "{\n\t.reg .pred p;\n\t"
            "mbarrier.try_wait.parity.acquire.cluster.shared::cta.b64 p, [%1], %2, 0x989680;\n\t"
            "selp.b32 %0, 1, 0, p;\n\t}"
            : "=r"(done) : "r"(a), "r"(parity) : "memory");
    } while (!done);
}
// Remote DSMEM float4 store.
__device__ __forceinline__ void dsmem_st4(unsigned laddr, unsigned rank,
                                          float4 v) {
    asm volatile(
        "{\n\t.reg .b32 ra;\n\t"
        "mapa.shared::cluster.u32 ra, %0, %1;\n\t"
        "st.shared::cluster.v4.b32 [ra], {%2, %3, %4, %5};\n\t}"
        :: "r"(laddr), "r"(rank), "f"(v.x), "f"(v.y), "f"(v.z), "f"(v.w)
        : "memory");
}

// ---------------------------------------------------------------------------
// GEMM: g_pre[m][j] = sum_k x[m][k] * W_ih[j][k] + b_ih[j] + b_hh[j]
// ---------------------------------------------------------------------------
#define BM 128
#define BN 64
#define BK 16

__global__ __launch_bounds__(256) void gemm_xw(
    const float* __restrict__ A,    // [M][256]
    const float* __restrict__ Wih,  // [512][256]
    const float* __restrict__ bih,
    const float* __restrict__ bhh)
{
    __shared__ float As[BK][BM + 4];
    __shared__ float Bs[BK][BN + 4];
    const int m0 = blockIdx.y * BM;
    const int n0 = blockIdx.x * BN;
    const int tid = threadIdx.x;
    const int ty = tid >> 4;
    const int tx = tid & 15;

    ull acc2[8][2];
#pragma unroll
    for (int i = 0; i < 8; ++i) { acc2[i][0] = 0ull; acc2[i][1] = 0ull; }

    for (int k0 = 0; k0 < NI; k0 += BK) {
#pragma unroll
        for (int i = 0; i < 2; ++i) {
            int f  = tid + i * 256;
            int r  = f >> 2;
            int c4 = f & 3;
            float4 v = *(const float4*)(A + (size_t)(m0 + r) * NI + k0 + c4 * 4);
            As[c4 * 4 + 0][r] = v.x;
            As[c4 * 4 + 1][r] = v.y;
            As[c4 * 4 + 2][r] = v.z;
            As[c4 * 4 + 3][r] = v.w;
        }
        {
            int r  = tid >> 2;
            int c4 = tid & 3;
            float4 v = *(const float4*)(Wih + (size_t)(n0 + r) * NI + k0 + c4 * 4);
            Bs[c4 * 4 + 0][r] = v.x;
            Bs[c4 * 4 + 1][r] = v.y;
            Bs[c4 * 4 + 2][r] = v.z;
            Bs[c4 * 4 + 3][r] = v.w;
        }
        __syncthreads();
#pragma unroll
        for (int k = 0; k < BK; ++k) {
            float a[8];
            *(float4*)&a[0] = *(const float4*)&As[k][ty * 8];
            *(float4*)&a[4] = *(const float4*)&As[k][ty * 8 + 4];
            ulonglong2 b2 = *(const ulonglong2*)&Bs[k][tx * 4];
#pragma unroll
            for (int i = 0; i < 8; ++i) {
                ull aa = pack2(a[i], a[i]);
                FFMA2(acc2[i][0], aa, b2.x, acc2[i][0]);
                FFMA2(acc2[i][1], aa, b2.y, acc2[i][1]);
            }
        }
        __syncthreads();
    }

    const int n = n0 + tx * 4;
    float4 bias = make_float4(bih[n + 0] + bhh[n + 0], bih[n + 1] + bhh[n + 1],
                              bih[n + 2] + bhh[n + 2], bih[n + 3] + bhh[n + 3]);
#pragma unroll
    for (int i = 0; i < 8; ++i) {
        float2 p0 = unpack2(acc2[i][0]);
        float2 p1 = unpack2(acc2[i][1]);
        float4 o;
        o.x = p0.x + bias.x;
        o.y = p0.y + bias.y;
        o.z = p1.x + bias.z;
        o.w = p1.y + bias.w;
        *(float4*)(g_pre + (size_t)(m0 + ty * 8 + i) * NH + n) = o;
    }
}

// ---------------------------------------------------------------------------
// Recurrence: 16 clusters x 8 CTAs. Cluster g owns batches [4g,4g+4);
// rank r owns columns [64r,64r+64). h exchange = DSMEM push into
// double-buffered peer smem + per-source mbarriers. No L2 on the
// critical path; hseq STG is output-only.
// 512 thr: warp w -> (ks=w>>1 consumed k-slice, ch=w&1 column half).
// ---------------------------------------------------------------------------
#define CL 8
#define RT 512

__global__ __launch_bounds__(RT, 1) __cluster_dims__(CL, 1, 1)
void rnn_recur(
    const float* __restrict__ h0,    // [B][H]
    const float* __restrict__ Whh,   // [H][H]
    float* __restrict__ hseq,        // [T][B][H]
    float* __restrict__ hlast)       // [B][H] or nullptr
{
    __shared__ float hbuf[2][4 * NH];        // h double buffer   (16 KB)
    __shared__ float part[2][16 * 4 * 32];   // partials/slot     (16 KB)
    __shared__ float hx[4 * 64];             // fresh local chunk ( 1 KB)
    __shared__ alignas(8) ull mb_full[8][2]; // [source rank][slot]
    __shared__ alignas(8) ull mb_empty[2];   // [slot]

    unsigned rank;
    asm("mov.u32 %0, %%cluster_ctarank;" : "=r"(rank));
    const int tid  = threadIdx.x;
    const int lane = tid & 31;
    const int w    = tid >> 5;            // warp 0..15
    const int ks   = w >> 1;              // consumed k-slice 0..7
    const int ch   = w & 1;               // column half
    const int cid  = blockIdx.x >> 3;     // cluster id = batch group
    const int b0   = cid * 4;
    const int j0   = (int)rank * 64;
    const int jc   = j0 + ch * 32 + lane; // output column this thread owns
    const int k0   = ks * 64;

    if (tid == 0) {
#pragma unroll
        for (int s = 0; s < 8; ++s) {
            mbar_init(smem_u32(&mb_full[s][0]), 32);  // one push warp, 32 lanes
            mbar_init(smem_u32(&mb_full[s][1]), 32);
        }
        mbar_init(smem_u32(&mb_empty[0]), 16);        // 16 consumer-warp lane0s
        mbar_init(smem_u32(&mb_empty[1]), 16);
    }

    // Prime hbuf[0] with h0 rows b0..b0+3 (full H, local).
    {
        int row = tid >> 7;
        int c4  = tid & 127;
        *(float4*)&hbuf[0][row * NH + c4 * 4] =
            __ldg((const float4*)(h0 + (size_t)(b0 + row) * NH + c4 * 4));
    }
    __syncthreads();
    asm volatile("barrier.cluster.arrive.aligned;" ::: "memory");
    asm volatile("barrier.cluster.wait.aligned;"   ::: "memory");

    // W_hh[jc][k0..k0+63] -> 32 packed-pair registers.
    ull w2[32];
    {
        const ulonglong2* wp =
            (const ulonglong2*)(Whh + (size_t)jc * NH + k0);
#pragma unroll
        for (int c = 0; c < 16; ++c) {
            ulonglong2 v = __ldg(wp + c);
            w2[2 * c]     = v.x;
            w2[2 * c + 1] = v.y;
        }
    }

    // Reduce/push role (warps 0..7): batch rb, column half rch.
    const int rb  = w >> 1;               // valid for w<8: batch 0..3
    const int rch = w & 1;
    const int rj  = j0 + rch * 32 + lane;
    float pre = 0.f;
    if (w < 8)
        pre = __ldg(g_pre + ((size_t)0 * NB + (b0 + rb)) * NH + rj);

    unsigned pf0 = 0, pf1 = 0;   // full[ks][slot] parities
    unsigned pe0 = 0, pe1 = 0;   // empty[slot]   parities (push warps)

    const unsigned a_full_ks0 = smem_u32(&mb_full[ks][0]);
    const unsigned a_full_my0 = smem_u32(&mb_full[rank][0]);
    const unsigned a_empty0   = smem_u32(&mb_empty[0]);

    for (int t = 0; t < T_SEQ; ++t) {
        const int slot = t & 1;
        const int q    = slot ^ 1;

        // Wait for my slice of hbuf[slot] (peers pushed it at t-1).
        if (t > 0) {
            if (slot) { mbar_wait(a_full_ks0 + 8, pf1); pf1 ^= 1; }
            else      { mbar_wait(a_full_ks0,     pf0); pf0 ^= 1; }
        }

        // 4 partial dots straight from local hbuf (broadcast LDS.128).
        float accs[4];
#pragma unroll
        for (int b = 0; b < 4; ++b) {
            const ulonglong2* hp =
                (const ulonglong2*)(&hbuf[slot][b * NH + k0]);
            ull a0 = 0ull, a1 = 0ull;
#pragma unroll
            for (int c = 0; c < 16; ++c) {
                ulonglong2 hv = hp[c];
                FFMA2(a0, w2[2 * c],     hv.x, a0);
                FFMA2(a1, w2[2 * c + 1], hv.y, a1);
            }
            float2 f0 = unpack2(a0);
            float2 f1 = unpack2(a1);
            accs[b] = (f0.x + f0.y) + (f1.x + f1.y);
        }
        // Done reading hbuf[slot]: signal its producer (rank ks).
        __syncwarp();
        if (lane == 0)
            mbar_arrive_rank(a_empty0 + (unsigned)slot * 8, (unsigned)ks);

#pragma unroll
        for (int b = 0; b < 4; ++b)
            part[slot][(w * 4 + b) * 32 + lane] = accs[b];
        __syncthreads();

        // ---- Reduce + tanh + emit + push (warps 0..7). ----
        if (w < 8) {
            float s = 0.f;
#pragma unroll
            for (int k2 = 0; k2 < 8; ++k2)
                s += part[slot][((k2 * 2 + rch) * 4 + rb) * 32 + lane];
            const float hv = tanhf(s + pre);
            const int   bo = b0 + rb;
            hseq[((size_t)t * NB + bo) * NH + rj] = hv;   // output only
            if (t == T_SEQ - 1 && hlast)
                hlast[(size_t)bo * NH + rj] = hv;
            hx[rb * 64 + rch * 32 + lane] = hv;
            if (t + 1 < T_SEQ)
                pre = __ldg(g_pre + ((size_t)(t + 1) * NB + bo) * NH + rj);

            asm volatile("bar.sync 1, 256;" ::: "memory");   // hx complete

            if (t < T_SEQ - 1) {
                // Backpressure: hbuf[q]'s readers (step t-1) must be done.
                if (t >= 1) {
                    if (q) { mbar_wait(a_empty0 + 8, pe1); pe1 ^= 1; }
                    else   { mbar_wait(a_empty0,     pe0); pe0 ^= 1; }
                }
                // Push full 4x64 chunk to rank w's hbuf[q] (+ self).
                const int li = lane * 8;
                const int br = li >> 6;
                const int cc = li & 63;
                float4 v0 = *(const float4*)&hx[li];
                float4 v1 = *(const float4*)&hx[li + 4];
                unsigned loc = smem_u32(&hbuf[q][br * NH + j0 + cc]);
                dsmem_st4(loc,      (unsigned)w, v0);
                dsmem_st4(loc + 16, (unsigned)w, v1);
                // Release-arrive: orders THIS lane's stores; all 32 arrive.
                mbar_arrive_rel_rank(a_full_my0 + (unsigned)q * 8,
                                     (unsigned)w);
            }
        }
    }

    // Keep smem alive until all peers' remote ops are done.
    asm volatile("barrier.cluster.arrive.aligned;" ::: "memory");
    asm volatile("barrier.cluster.wait.aligned;"   ::: "memory");
}

// ---------------------------------------------------------------------------
extern "C" void kernel_launch(void* const* d_in, const int* in_sizes, int n_in,
                              void* d_out, int out_size)
{
    const float* x   = (const float*)d_in[0];
    const float* h0  = (const float*)d_in[1];
    const float* Wih = (const float*)d_in[2];
    const float* Whh = (const float*)d_in[3];
    const float* bih = (const float*)d_in[4];
    const float* bhh = (const float*)d_in[5];
    float* out = (float*)d_out;

    float* hlast = nullptr;
    if (out_size >= (int)((size_t)T_SEQ * NB * NH + NB * NH))
        hlast = out + (size_t)T_SEQ * NB * NH;

    dim3 grid(NH / BN, (T_SEQ * NB) / BM);   // (8, 256)
    gemm_xw<<<grid, 256>>>(x, Wih, bih, bhh);

    rnn_recur<<<128, RT>>>(h0, Whh, out, hlast);
}

// round 16
// speedup vs baseline: 1.4181x; 1.4181x over previous
#include <cuda_runtime.h>
#include <math.h>

#define T_SEQ 512
#define NB    64
#define NI    256
#define NH    512

// Input-projection scratch + per-(bt,jt) flags. Flags are MONOTONIC across
// graph replays: exactly 8*T_SEQ = 4096 increments per flag per launch
// (8 reducer warps x 512 steps, single CTA owner). All flags are equal at
// every launch boundary; a CTA reads its OWN (not yet incremented) flag as
// the launch base. Comparisons are wrap-safe (signed difference).
__device__ float    g_pre[(size_t)T_SEQ * NB * NH];
__device__ unsigned g_prog[128 * 64];   // 256 B apart

typedef unsigned long long ull;

// Packed 2x fp32 FMA (sm_10x f32x2 pipe).
#define FFMA2(d, a, b, c) \
    asm("fma.rn.f32x2 %0, %1, %2, %3;" : "=l"(d) : "l"(a), "l"(b), "l"(c))

__device__ __forceinline__ ull pack2(float lo, float hi) {
    ull r;
    asm("mov.b64 %0, {%1, %2};"
        : "=l"(r) : "r"(__float_as_uint(lo)), "r"(__float_as_uint(hi)));
    return r;
}
__device__ __forceinline__ float2 unpack2(ull v) {
    unsigned lo, hi;
    asm("mov.b64 {%0, %1}, %2;" : "=r"(lo), "=r"(hi) : "l"(v));
    return make_float2(__uint_as_float(lo), __uint_as_float(hi));
}
// Poll a flag until it reaches `need` (acquire orders subsequent loads).
__device__ __forceinline__ void flag_wait(const unsigned* f, unsigned need) {
    unsigned v;
    do {
        asm volatile("ld.acquire.gpu.u32 %0, [%1];"
                     : "=r"(v) : "l"(f) : "memory");
    } while ((int)(v - need) < 0);
}

// ---------------------------------------------------------------------------
// GEMM: g_pre[m][j] = sum_k x[m][k] * W_ih[j][k] + b_ih[j] + b_hh[j]
// ---------------------------------------------------------------------------
#define BM 128
#define BN 64
#define BK 16

__global__ __launch_bounds__(256) void gemm_xw(
    const float* __restrict__ A,    // [M][256]
    const float* __restrict__ Wih,  // [512][256]
    const float* __restrict__ bih,
    const float* __restrict__ bhh)
{
    __shared__ float As[BK][BM + 4];
    __shared__ float Bs[BK][BN + 4];
    const int m0 = blockIdx.y * BM;
    const int n0 = blockIdx.x * BN;
    const int tid = threadIdx.x;
    const int ty = tid >> 4;
    const int tx = tid & 15;

    ull acc2[8][2];
#pragma unroll
    for (int i = 0; i < 8; ++i) { acc2[i][0] = 0ull; acc2[i][1] = 0ull; }

    for (int k0 = 0; k0 < NI; k0 += BK) {
#pragma unroll
        for (int i = 0; i < 2; ++i) {
            int f  = tid + i * 256;
            int r  = f >> 2;
            int c4 = f & 3;
            float4 v = *(const float4*)(A + (size_t)(m0 + r) * NI + k0 + c4 * 4);
            As[c4 * 4 + 0][r] = v.x;
            As[c4 * 4 + 1][r] = v.y;
            As[c4 * 4 + 2][r] = v.z;
            As[c4 * 4 + 3][r] = v.w;
        }
        {
            int r  = tid >> 2;
            int c4 = tid & 3;
            float4 v = *(const float4*)(Wih + (size_t)(n0 + r) * NI + k0 + c4 * 4);
            Bs[c4 * 4 + 0][r] = v.x;
            Bs[c4 * 4 + 1][r] = v.y;
            Bs[c4 * 4 + 2][r] = v.z;
            Bs[c4 * 4 + 3][r] = v.w;
        }
        __syncthreads();
#pragma unroll
        for (int k = 0; k < BK; ++k) {
            float a[8];
            *(float4*)&a[0] = *(const float4*)&As[k][ty * 8];
            *(float4*)&a[4] = *(const float4*)&As[k][ty * 8 + 4];
            ulonglong2 b2 = *(const ulonglong2*)&Bs[k][tx * 4];
#pragma unroll
            for (int i = 0; i < 8; ++i) {
                ull aa = pack2(a[i], a[i]);
                FFMA2(acc2[i][0], aa, b2.x, acc2[i][0]);
                FFMA2(acc2[i][1], aa, b2.y, acc2[i][1]);
            }
        }
        __syncthreads();
    }

    const int n = n0 + tx * 4;
    float4 bias = make_float4(bih[n + 0] + bhh[n + 0], bih[n + 1] + bhh[n + 1],
                              bih[n + 2] + bhh[n + 2], bih[n + 3] + bhh[n + 3]);
#pragma unroll
    for (int i = 0; i < 8; ++i) {
        float2 p0 = unpack2(acc2[i][0]);
        float2 p1 = unpack2(acc2[i][1]);
        float4 o;
        o.x = p0.x + bias.x;
        o.y = p0.y + bias.y;
        o.z = p1.x + bias.z;
        o.w = p1.y + bias.w;
        *(float4*)(g_pre + (size_t)(m0 + ty * 8 + i) * NH + n) = o;
    }
}

// ---------------------------------------------------------------------------
// Recurrence: 128 CTAs (16 jt x 8 bt), 256 thr. warp = k-slice (dots) and
// warp = batch (reduce). ONE bar.sync per step; publish is per-reduce-warp
// (red.release +1, 8 per flag per step), waits are per-consumer-warp.
// Partials double-buffered by step parity for cross-step safety.
// ---------------------------------------------------------------------------
#define RT 256

__global__ __launch_bounds__(RT, 1) void rnn_recur(
    const float* __restrict__ h0,    // [B][H]
    const float* __restrict__ Whh,   // [H][H]
    float* __restrict__ hseq,        // [T][B][H]
    float* __restrict__ hlast)       // [B][H] or nullptr
{
    __shared__ float hs[8 * NH];           // h staging, warp-private cols (16 KB)
    __shared__ float part[2][8 * 8 * 32];  // partials double buffer      (16 KB)
    __shared__ unsigned sbase;

    const int tid  = threadIdx.x;
    const int lane = tid & 31;
    const int warp = tid >> 5;
    const int jt   = blockIdx.x & 15;
    const int bt   = blockIdx.x >> 4;
    const int j0   = jt * 32;
    const int b0   = bt * 8;
    const int ks   = warp;                // consumed k-slice
    const int k0   = ks * 64;

    unsigned* const flag_own = &g_prog[(bt * 16 + jt) * 64];
    const unsigned* const fA = &g_prog[(bt * 16 + 2 * ks)     * 64];
    const unsigned* const fB = &g_prog[(bt * 16 + 2 * ks + 1) * 64];

    if (tid == 0) sbase = *(volatile unsigned*)flag_own;
    __syncthreads();
    const unsigned base = sbase;

    // W_hh[j0+lane][k0..k0+63] -> 32 packed-pair registers.
    ull w2[32];
    {
        const ulonglong2* wp =
            (const ulonglong2*)(Whh + (size_t)(j0 + lane) * NH + k0);
#pragma unroll
        for (int c = 0; c < 16; ++c) {
            ulonglong2 v = __ldg(wp + c);
            w2[2 * c]     = v.x;
            w2[2 * c + 1] = v.y;
        }
    }

    // Reduce-role identity: batch row = warp, column = j0+lane.
    float pre = __ldg(g_pre + ((size_t)0 * NB + (b0 + warp)) * NH + j0 + lane);

    for (int t = 0; t < T_SEQ; ++t) {
        const int slot = t & 1;

        // Per-warp dependency wait: my k-slice's 2 producer CTAs at t-1
        // (8 reducer-warp increments per step per flag).
        if (t > 0) {
            const unsigned need = base + (unsigned)(8 * t);
            flag_wait(fA, need);
            flag_wait(fB, need);
        }

        // Stage OWN h slice (8 batches x 64 cols) — warp-private columns.
        const float* hprev = t ? hseq + (size_t)(t - 1) * NB * NH : h0;
#pragma unroll
        for (int i = 0; i < 4; ++i) {
            int idx = lane + 32 * i;       // 0..127 float4 slots
            int row = idx >> 4;
            int c4  = idx & 15;
            float4 v = __ldcg((const float4*)(hprev +
                          (size_t)(b0 + row) * NH + k0 + c4 * 4));
            *(float4*)(hs + row * NH + k0 + c4 * 4) = v;
        }
        __syncwarp();

        // 8 partial dots (one per batch), K-slice 64, packed FMAs.
        float accs[8];
#pragma unroll
        for (int b = 0; b < 8; ++b) {
            const ulonglong2* hp = (const ulonglong2*)(hs + b * NH + k0);
            ull a0 = 0ull, a1 = 0ull;
#pragma unroll
            for (int c = 0; c < 16; ++c) {
                ulonglong2 hv = hp[c];   // broadcast LDS.128
                FFMA2(a0, w2[2 * c],     hv.x, a0);
                FFMA2(a1, w2[2 * c + 1], hv.y, a1);
            }
            float2 f0 = unpack2(a0);
            float2 f1 = unpack2(a1);
            accs[b] = (f0.x + f0.y) + (f1.x + f1.y);
        }
#pragma unroll
        for (int b = 0; b < 8; ++b)
            part[slot][ks * 256 + b * 32 + lane] = accs[b];

        // The ONLY CTA-wide sync of the step (partials ready; also the
        // cross-step fence that makes slot reuse at t+2 safe).
        __syncthreads();

        // Reduce + tanh + emit + per-warp publish. No trailing barrier:
        // this warp immediately proceeds to its next-step wait/staging.
        float s = 0.f;
#pragma unroll
        for (int w = 0; w < 8; ++w)
            s += part[slot][w * 256 + warp * 32 + lane];
        const float hv = tanhf(s + pre);
        const int   bo = b0 + warp;
        hseq[((size_t)t * NB + bo) * NH + j0 + lane] = hv;
        if (t == T_SEQ - 1 && hlast)
            hlast[(size_t)bo * NH + j0 + lane] = hv;

        // Prefetch next step's pre (off the critical chain).
        if (t + 1 < T_SEQ)
            pre = __ldg(g_pre + ((size_t)(t + 1) * NB + bo) * NH + j0 + lane);

        // Publish: __syncwarp orders all 32 lanes' STG before lane0's
        // release-increment (same pattern as CTA-level CG sync, warp scope).
        __syncwarp();
        if (lane == 0)
            asm volatile("red.release.gpu.global.add.u32 [%0], 1;"
                         :: "l"(flag_own) : "memory");
    }
}

// ---------------------------------------------------------------------------
extern "C" void kernel_launch(void* const* d_in, const int* in_sizes, int n_in,
                              void* d_out, int out_size)
{
    const float* x   = (const float*)d_in[0];
    const float* h0  = (const float*)d_in[1];
    const float* Wih = (const float*)d_in[2];
    const float* Whh = (const float*)d_in[3];
    const float* bih = (const float*)d_in[4];
    const float* bhh = (const float*)d_in[5];
    float* out = (float*)d_out;

    float* hlast = nullptr;
    if (out_size >= (int)((size_t)T_SEQ * NB * NH + NB * NH))
        hlast = out + (size_t)T_SEQ * NB * NH;

    dim3 grid(NH / BN, (T_SEQ * NB) / BM);   // (8, 256)
    gemm_xw<<<grid, 256>>>(x, Wih, bih, bhh);

    rnn_recur<<<128, RT>>>(h0, Whh, out, hlast);
}

// round 17
// speedup vs baseline: 1.6696x; 1.1773x over previous
#include <cuda_runtime.h>
#include <math.h>

#define T_SEQ 512
#define NB    64
#define NI    256
#define NH    512

// Per-batch-group barrier counters: MONOTONIC across graph replays, never
// reset. Each launch adds exactly 512*16 = 8192 arrivals per counter, so
// base = value & ~8191 read before this CTA's first arrival is correct.
__device__ unsigned g_barg[8 * 64];   // 8 counters, 256 B apart

typedef unsigned long long ull;

// Packed 2x fp32 FMA (sm_10x f32x2 pipe).
#define FFMA2(d, a, b, c) \
    asm("fma.rn.f32x2 %0, %1, %2, %3;" : "=l"(d) : "l"(a), "l"(b), "l"(c))

__device__ __forceinline__ float2 unpack2(ull v) {
    unsigned lo, hi;
    asm("mov.b64 {%0, %1}, %2;" : "=r"(lo), "=r"(hi) : "l"(v));
    return make_float2(__uint_as_float(lo), __uint_as_float(hi));
}

__device__ __forceinline__ unsigned smem_u32(const void* p) {
    return (unsigned)__cvta_generic_to_shared(p);
}
__device__ __forceinline__ void mbar_init(unsigned a, unsigned cnt) {
    asm volatile("mbarrier.init.shared.b64 [%0], %1;" :: "r"(a), "r"(cnt)
                 : "memory");
}
__device__ __forceinline__ void mbar_arrive(unsigned a) {
    asm volatile("mbarrier.arrive.release.cta.shared.b64 _, [%0];"
                 :: "r"(a) : "memory");
}
__device__ __forceinline__ void mbar_wait(unsigned a, unsigned parity) {
    unsigned done;
    do {
        asm volatile(
            "{\n\t.reg .pred p;\n\t"
            "mbarrier.try_wait.parity.acquire.cta.shared.b64 p, [%1], %2, 0x989680;\n\t"
            "selp.b32 %0, 1, 0, p;\n\t}"
            : "=r"(done) : "r"(a), "r"(parity) : "memory");
    } while (!done);
}

// ---- dynamic smem layout (float indices) ----------------------------------
#define HS_OFF    0       // h tile [8 b][512]                  (16 KB)
#define PART_OFF  4096    // consumer partials [8 ks][8 b][32]  ( 8 KB)
#define RING_OFF  6144    // pre ring [2 slot][8 b][32 j]       ( 2 KB)
#define XB_OFF    6656    // x tile [8 b][256]                  ( 8 KB)
#define PP_OFF    8704    // producer partials [4 pw][8 b][32]  ( 4 KB)
#define MBAR_OFF  9728    // full0, full1, empty0, empty1 (4x u64) + base
#define SM_FLOATS 9744

// ARBITER NOTE: warp scheduler is highest-wid-first. Producers take warps
// 0..3 (lowest priority, fill idle slots); consumers take warps 4..11
// (highest priority — the serial recurrence chain never yields to producers).
#define RT 384

__global__ __launch_bounds__(RT, 1) void rnn_fused(
    const float* __restrict__ x,     // [T][B][I]
    const float* __restrict__ h0,    // [B][H]
    const float* __restrict__ Wih,   // [H][I]
    const float* __restrict__ Whh,   // [H][H]
    const float* __restrict__ bih,   // [H]
    const float* __restrict__ bhh,   // [H]
    float* __restrict__ hseq,        // [T][B][H]
    float* __restrict__ hlast)       // [B][H] or nullptr
{
    extern __shared__ float sm[];

    const int tid  = threadIdx.x;
    const int lane = tid & 31;
    const int warp = tid >> 5;
    const int jt   = blockIdx.x & 15;
    const int bt   = blockIdx.x >> 4;
    const int j0   = jt * 32;
    const int b0   = bt * 8;
    unsigned* const bar = &g_barg[bt * 64];

    const unsigned a_full0  = smem_u32(sm + MBAR_OFF);       // +0 / +8
    const unsigned a_empty0 = smem_u32(sm + MBAR_OFF + 4);   // +0 / +8
    unsigned* const pbase   = (unsigned*)(sm + MBAR_OFF + 8);

    if (tid == 0) {
        mbar_init(a_full0,      4);   // 4 producer warps arrive
        mbar_init(a_full0  + 8, 4);
        mbar_init(a_empty0,     8);   // 8 consumer warps arrive
        mbar_init(a_empty0 + 8, 8);
        *pbase = (*(volatile unsigned*)bar) & ~8191u;
    }
    __syncthreads();
    const unsigned base = *pbase;

    if (warp >= 4) {
        // ========== CONSUMER (recurrence) — warps 4..11, HIGH priority ====
        const int ks = warp - 4;      // k-slice this warp computes, 0..7
        const int k0 = ks * 64;

        // W_hh[j0+lane][k0..k0+63] -> 32 packed-pair registers.
        ull w2[32];
        {
            const ulonglong2* wp =
                (const ulonglong2*)(Whh + (size_t)(j0 + lane) * NH + k0);
#pragma unroll
            for (int c = 0; c < 16; ++c) {
                ulonglong2 v = __ldg(wp + c);
                w2[2 * c]     = v.x;
                w2[2 * c + 1] = v.y;
            }
        }

        unsigned pf0 = 0, pf1 = 0;    // full-ring parities per slot

        for (int t = 0; t < T_SEQ; ++t) {
            const int slot = t & 1;

            // Stage OWN h slice (8 batches x 64 cols) — warp-private.
            const float* hprev = t ? hseq + (size_t)(t - 1) * NB * NH : h0;
#pragma unroll
            for (int i = 0; i < 4; ++i) {
                int idx = lane + 32 * i;       // 0..127 float4 slots
                int row = idx >> 4;
                int c4  = idx & 15;
                float4 v = __ldcg((const float4*)(hprev +
                              (size_t)(b0 + row) * NH + k0 + c4 * 4));
                *(float4*)(sm + HS_OFF + row * NH + k0 + c4 * 4) = v;
            }
            __syncwarp();

            // 8 partial dots (one per batch), K-slice 64, packed FMAs.
            float accs[8];
#pragma unroll
            for (int b = 0; b < 8; ++b) {
                const ulonglong2* hp =
                    (const ulonglong2*)(sm + HS_OFF + b * NH + k0);
                ull a0 = 0ull, a1 = 0ull;
#pragma unroll
                for (int c = 0; c < 16; ++c) {
                    ulonglong2 hv = hp[c];   // broadcast LDS.128 (1 phase)
                    FFMA2(a0, w2[2 * c],     hv.x, a0);
                    FFMA2(a1, w2[2 * c + 1], hv.y, a1);
                }
                float2 f0 = unpack2(a0);
                float2 f1 = unpack2(a1);
                accs[b] = (f0.x + f0.y) + (f1.x + f1.y);
            }
#pragma unroll
            for (int b = 0; b < 8; ++b)
                sm[PART_OFF + ks * 256 + b * 32 + lane] = accs[b];
            asm volatile("bar.sync 1, 256;" ::: "memory");

            // Reduce role: ks = batch row, lane = column j0+lane.
            float s = 0.f;
#pragma unroll
            for (int w = 0; w < 8; ++w)
                s += sm[PART_OFF + w * 256 + ks * 32 + lane];

            // pre[t] ring read (producers had a full step of slack).
            if (slot) { mbar_wait(a_full0 + 8, pf1); pf1 ^= 1; }
            else      { mbar_wait(a_full0,     pf0); pf0 ^= 1; }
            const float pre = sm[RING_OFF + slot * 256 + ks * 32 + lane];

            const float hv = tanhf(s + pre);
            const int   bo = b0 + ks;
            hseq[((size_t)t * NB + bo) * NH + j0 + lane] = hv;
            if (t == T_SEQ - 1 && hlast)
                hlast[(size_t)bo * NH + j0 + lane] = hv;

            // Ring slot consumed -> producers may refill it.
            __syncwarp();
            if (lane == 0) mbar_arrive(a_empty0 + (unsigned)slot * 8);

            asm volatile("bar.sync 1, 256;" ::: "memory");
            // Group barrier: 16 CTAs sharing bt. Final step: arrive only.
            if (tid == 128) {   // first consumer thread (warp 4, lane 0)
                asm volatile("red.release.gpu.global.add.u32 [%0], 1;"
                             :: "l"(bar) : "memory");
                if (t != T_SEQ - 1) {
                    const unsigned target = base + (unsigned)(t + 1) * 16u;
                    unsigned f;
                    do {
                        asm volatile("ld.acquire.gpu.u32 %0, [%1];"
                                     : "=r"(f) : "l"(bar) : "memory");
                    } while (f < target);
                }
            }
            if (t != T_SEQ - 1)
                asm volatile("bar.sync 1, 256;" ::: "memory");
        }
    } else {
        // ===== PRODUCER (input projection) — warps 0..3, LOW priority =====
        const int pw   = warp;        // 0..3
        const int k0   = pw * 64;     // producer k-slice of NI
        const int ptid = tid;         // 0..127

        // W_ih[j0+lane][k0..k0+63] -> 32 packed-pair registers.
        ull wi2[32];
        {
            const ulonglong2* wp =
                (const ulonglong2*)(Wih + (size_t)(j0 + lane) * NI + k0);
#pragma unroll
            for (int c = 0; c < 16; ++c) {
                ulonglong2 v = __ldg(wp + c);
                wi2[2 * c]     = v.x;
                wi2[2 * c + 1] = v.y;
            }
        }
        const float bias = __ldg(bih + j0 + lane) + __ldg(bhh + j0 + lane);
        unsigned pe0 = 0, pe1 = 0;

        for (int t = 0; t < T_SEQ; ++t) {
            const int slot = t & 1;

            // Stage x tile (8 batches x 256) — 128 threads x 4 float4.
#pragma unroll
            for (int i = 0; i < 4; ++i) {
                int idx = ptid + 128 * i;      // 0..511 float4 slots
                int row = idx >> 6;
                int c4  = idx & 63;
                float4 v = __ldg((const float4*)(x +
                              ((size_t)t * NB + b0 + row) * NI + c4 * 4));
                *(float4*)(sm + XB_OFF + row * NI + c4 * 4) = v;
            }
            asm volatile("bar.sync 2, 128;" ::: "memory");

            // 8 partial dots over this warp's 64-k slice (broadcast LDS).
            float pacc[8];
#pragma unroll
            for (int b = 0; b < 8; ++b) {
                const ulonglong2* xp =
                    (const ulonglong2*)(sm + XB_OFF + b * NI + k0);
                ull a0 = 0ull, a1 = 0ull;
#pragma unroll
                for (int c = 0; c < 16; ++c) {
                    ulonglong2 xv = xp[c];   // broadcast LDS.128 (1 phase)
                    FFMA2(a0, wi2[2 * c],     xv.x, a0);
                    FFMA2(a1, wi2[2 * c + 1], xv.y, a1);
                }
                float2 f0 = unpack2(a0);
                float2 f1 = unpack2(a1);
                pacc[b] = (f0.x + f0.y) + (f1.x + f1.y);
            }
#pragma unroll
            for (int b = 0; b < 8; ++b)
                sm[PP_OFF + pw * 256 + b * 32 + lane] = pacc[b];
            asm volatile("bar.sync 2, 128;" ::: "memory");

            // Wait for ring slot to be free (consumers of step t-2 done).
            if (t >= 2) {
                if (slot) { mbar_wait(a_empty0 + 8, pe1); pe1 ^= 1; }
                else      { mbar_wait(a_empty0,     pe0); pe0 ^= 1; }
            }

            // Reduce: warp pw emits batches 2pw and 2pw+1.
#pragma unroll
            for (int r = 0; r < 2; ++r) {
                const int b = pw * 2 + r;
                float s = bias;
#pragma unroll
                for (int w = 0; w < 4; ++w)
                    s += sm[PP_OFF + w * 256 + b * 32 + lane];
                sm[RING_OFF + slot * 256 + b * 32 + lane] = s;
            }
            __syncwarp();
            if (lane == 0) mbar_arrive(a_full0 + (unsigned)slot * 8);
        }
    }
}

// ---------------------------------------------------------------------------
extern "C" void kernel_launch(void* const* d_in, const int* in_sizes, int n_in,
                              void* d_out, int out_size)
{
    const float* x   = (const float*)d_in[0];
    const float* h0  = (const float*)d_in[1];
    const float* Wih = (const float*)d_in[2];
    const float* Whh = (const float*)d_in[3];
    const float* bih = (const float*)d_in[4];
    const float* bhh = (const float*)d_in[5];
    float* out = (float*)d_out;

    float* hlast = nullptr;
    if (out_size >= (int)((size_t)T_SEQ * NB * NH + NB * NH))
        hlast = out + (size_t)T_SEQ * NB * NH;

    const size_t smem = SM_FLOATS * sizeof(float);   // 38976 B
    cudaFuncSetAttribute(rnn_fused,
                         cudaFuncAttributeMaxDynamicSharedMemorySize,
                         (int)smem);
    rnn_fused<<<128, RT, smem>>>(x, h0, Wih, Whh, bih, bhh, out, hlast);
}